// round 15
// baseline (speedup 1.0000x reference)
#include <cuda_runtime.h>

// Problem constants (shapes fixed by the dataset)
#define B_DIM 8192
#define T_DIM 64
#define D_DIM 64
#define H_DIM 256
#define L_DIM 64
#define K_DIM 128   // D + L
// n_shifts == T_DIM == 64

// Scratch for ko_W powers: g_Wpow[t] = ko_W^t (t = 1..63). 4 MB device global.
__device__ float g_Wpow[64][128 * 128];

// ---------------------------------------------------------------------------
// Packed f32x2 helpers (Blackwell FFMA2 — only reachable via PTX fma.rn.f32x2)
// ---------------------------------------------------------------------------
__device__ __forceinline__ unsigned long long pack2(float a) {
    unsigned long long r;
    asm("mov.b64 %0, {%1, %1};" : "=l"(r) : "r"(__float_as_uint(a)));
    return r;
}
__device__ __forceinline__ void ffma2(unsigned long long& d,
                                      unsigned long long a,
                                      unsigned long long b) {
    asm("fma.rn.f32x2 %0, %1, %2, %0;" : "+l"(d) : "l"(a), "l"(b));
}
__device__ __forceinline__ float2 unpack2(unsigned long long v) {
    unsigned lo, hi;
    asm("mov.b64 {%0, %1}, %2;" : "=r"(lo), "=r"(hi) : "l"(v));
    return make_float2(__uint_as_float(lo), __uint_as_float(hi));
}

// ---------------------------------------------------------------------------
// Kernel 1: fused MLP. One CTA = 64 rows of M = B*T.
//   h0 = relu(x @ W0 + b0); h1 = relu(h0 @ W1 + b1); z = h1 @ W2
//   enc_gt row = [x_row (64), z_row (64)]
// smem: sX 64x65 | sH 64x258 | sW 64x256 (staging for W0 / W1 chunks / W2 / z)
// ---------------------------------------------------------------------------
#define SX_STRIDE 65
#define SH_STRIDE 258
#define SMEM_MLP ((64 * SX_STRIDE + 64 * SH_STRIDE + 64 * 256) * 4)

__global__ void __launch_bounds__(256, 1) mlp_kernel(
    const float* __restrict__ x,
    const float* __restrict__ W0, const float* __restrict__ b0,
    const float* __restrict__ W1, const float* __restrict__ b1,
    const float* __restrict__ W2,
    float* __restrict__ out_gt)
{
    extern __shared__ float smem[];
    float* sX = smem;                       // 64 x 65
    float* sH = sX + 64 * SX_STRIDE;        // 64 x 258
    float* sW = sH + 64 * SH_STRIDE;        // 16384 floats staging

    const int tid = threadIdx.x;
    const int tx = tid & 15;                // column group
    const int ty = tid >> 4;                // row group (4 rows each)
    const long long m0 = (long long)blockIdx.x * 64;

    // ---- load x tile (64x64) into padded sX; load W0 (64x256) into sW ----
    {
        const float4* xg = (const float4*)(x + m0 * D_DIM);
        #pragma unroll
        for (int idx = tid; idx < 1024; idx += 256) {
            float4 v = xg[idx];
            int r = idx >> 4, c = (idx & 15) << 2;
            float* d = sX + r * SX_STRIDE + c;
            d[0] = v.x; d[1] = v.y; d[2] = v.z; d[3] = v.w;
        }
        const float4* wg = (const float4*)W0;
        float4* ws = (float4*)sW;
        #pragma unroll
        for (int idx = tid; idx < 4096; idx += 256) ws[idx] = wg[idx];
    }
    __syncthreads();

    // ---- GEMM1: h0 = relu(sX @ W0 + b0), K = 64, out 64x256 ----
    unsigned long long acc[4][8];
    #pragma unroll
    for (int j = 0; j < 8; j++) {
        unsigned long long bp = *(const unsigned long long*)(b0 + 2 * tx + 32 * j);
        #pragma unroll
        for (int i = 0; i < 4; i++) acc[i][j] = bp;
    }
    #pragma unroll 4
    for (int k = 0; k < 64; k++) {
        unsigned long long b2[8];
        #pragma unroll
        for (int j = 0; j < 8; j++)
            b2[j] = *(const unsigned long long*)(sW + k * 256 + 2 * tx + 32 * j);
        #pragma unroll
        for (int i = 0; i < 4; i++) {
            unsigned long long a2 = pack2(sX[(ty * 4 + i) * SX_STRIDE + k]);
            #pragma unroll
            for (int j = 0; j < 8; j++) ffma2(acc[i][j], a2, b2[j]);
        }
    }
    #pragma unroll
    for (int i = 0; i < 4; i++) {
        #pragma unroll
        for (int j = 0; j < 8; j++) {
            float2 v = unpack2(acc[i][j]);
            v.x = fmaxf(v.x, 0.f); v.y = fmaxf(v.y, 0.f);
            *(float2*)(sH + (ty * 4 + i) * SH_STRIDE + 2 * tx + 32 * j) = v;
        }
    }
    __syncthreads();

    // ---- GEMM2: h1 = relu(h0 @ W1 + b1), K = 256 streamed in 4 chunks ----
    #pragma unroll
    for (int j = 0; j < 8; j++) {
        unsigned long long bp = *(const unsigned long long*)(b1 + 2 * tx + 32 * j);
        #pragma unroll
        for (int i = 0; i < 4; i++) acc[i][j] = bp;
    }
    for (int kc = 0; kc < 4; kc++) {
        const float4* wg = (const float4*)(W1 + kc * 64 * 256);
        float4* ws = (float4*)sW;
        #pragma unroll
        for (int idx = tid; idx < 4096; idx += 256) ws[idx] = wg[idx];
        __syncthreads();
        #pragma unroll 4
        for (int kk = 0; kk < 64; kk++) {
            const int k = kc * 64 + kk;
            unsigned long long b2[8];
            #pragma unroll
            for (int j = 0; j < 8; j++)
                b2[j] = *(const unsigned long long*)(sW + kk * 256 + 2 * tx + 32 * j);
            #pragma unroll
            for (int i = 0; i < 4; i++) {
                unsigned long long a2 = pack2(sH[(ty * 4 + i) * SH_STRIDE + k]);
                #pragma unroll
                for (int j = 0; j < 8; j++) ffma2(acc[i][j], a2, b2[j]);
            }
        }
        __syncthreads();
    }
    // relu, overwrite sH with h1 (all reads of h0 done); stage W2 into sW
    #pragma unroll
    for (int i = 0; i < 4; i++) {
        #pragma unroll
        for (int j = 0; j < 8; j++) {
            float2 v = unpack2(acc[i][j]);
            v.x = fmaxf(v.x, 0.f); v.y = fmaxf(v.y, 0.f);
            *(float2*)(sH + (ty * 4 + i) * SH_STRIDE + 2 * tx + 32 * j) = v;
        }
    }
    {
        const float4* wg = (const float4*)W2;   // 256x64
        float4* ws = (float4*)sW;
        #pragma unroll
        for (int idx = tid; idx < 4096; idx += 256) ws[idx] = wg[idx];
    }
    __syncthreads();

    // ---- GEMM3: z = h1 @ W2, K = 256, out 64x64 ----
    unsigned long long acc3[4][2];
    #pragma unroll
    for (int i = 0; i < 4; i++) { acc3[i][0] = 0ULL; acc3[i][1] = 0ULL; }
    #pragma unroll 4
    for (int k = 0; k < 256; k++) {
        unsigned long long c0 = *(const unsigned long long*)(sW + k * 64 + 2 * tx);
        unsigned long long c1 = *(const unsigned long long*)(sW + k * 64 + 2 * tx + 32);
        #pragma unroll
        for (int i = 0; i < 4; i++) {
            unsigned long long a2 = pack2(sH[(ty * 4 + i) * SH_STRIDE + k]);
            ffma2(acc3[i][0], a2, c0);
            ffma2(acc3[i][1], a2, c1);
        }
    }
    __syncthreads();
    // stage z (64x64) into sW for coalesced output
    #pragma unroll
    for (int i = 0; i < 4; i++) {
        #pragma unroll
        for (int j = 0; j < 2; j++) {
            float2 v = unpack2(acc3[i][j]);
            *(float2*)(sW + (ty * 4 + i) * 64 + 2 * tx + 32 * j) = v;
        }
    }
    __syncthreads();

    // ---- write enc_gt tile: 64 rows x 128 cols ([x | z]) ----
    #pragma unroll
    for (int idx = tid; idx < 2048; idx += 256) {
        int r = idx >> 5, c4 = idx & 31;
        float4 v;
        if (c4 < 16) {
            const float* s = sX + r * SX_STRIDE + (c4 << 2);
            v = make_float4(s[0], s[1], s[2], s[3]);
        } else {
            const float* s = sW + r * 64 + ((c4 - 16) << 2);
            v = make_float4(s[0], s[1], s[2], s[3]);
        }
        *(float4*)(out_gt + (m0 + r) * K_DIM + (c4 << 2)) = v;
    }
}

// ---------------------------------------------------------------------------
// Kernel 2a: seed P[1] = ko_W
// ---------------------------------------------------------------------------
__global__ void copy_w_kernel(const float* __restrict__ koW)
{
    int i = blockIdx.x * 256 + threadIdx.x;
    g_Wpow[1][i] = koW[i];
}

// ---------------------------------------------------------------------------
// Kernel 2b: doubling step. Block b computes P[b+1+m] = P[b+1] @ P[m].
// ---------------------------------------------------------------------------
#define SMEM_POW ((128 * 130 + 128 * 128) * 4)

__global__ void __launch_bounds__(256, 1) pow_step_kernel(int m)
{
    const int i = blockIdx.x + 1;
    const float* A  = g_Wpow[i];
    const float* Bm = g_Wpow[m];
    float* C = g_Wpow[i + m];

    extern __shared__ float s[];
    float* sA = s;                  // 128 x 130 (padded)
    float* sB = sA + 128 * 130;     // 128 x 128
    const int tid = threadIdx.x;

    for (int idx = tid; idx < 4096; idx += 256) {
        float4 v = ((const float4*)A)[idx];
        int r = idx >> 5, c = (idx & 31) << 2;
        float* d = sA + r * 130 + c;
        d[0] = v.x; d[1] = v.y; d[2] = v.z; d[3] = v.w;
        ((float4*)sB)[idx] = ((const float4*)Bm)[idx];
    }
    __syncthreads();

    const int tx = tid & 15, ty = tid >> 4;   // 8 rows x 8 cols per thread
    unsigned long long acc[8][4];
    #pragma unroll
    for (int r = 0; r < 8; r++)
        #pragma unroll
        for (int j = 0; j < 4; j++) acc[r][j] = 0ULL;

    #pragma unroll 2
    for (int k = 0; k < 128; k++) {
        unsigned long long b2[4];
        #pragma unroll
        for (int j = 0; j < 4; j++)
            b2[j] = *(const unsigned long long*)(sB + k * 128 + 2 * tx + 32 * j);
        #pragma unroll
        for (int r = 0; r < 8; r++) {
            unsigned long long a2 = pack2(sA[(ty * 8 + r) * 130 + k]);
            #pragma unroll
            for (int j = 0; j < 4; j++) ffma2(acc[r][j], a2, b2[j]);
        }
    }
    #pragma unroll
    for (int r = 0; r < 8; r++)
        #pragma unroll
        for (int j = 0; j < 4; j++) {
            float2 v = unpack2(acc[r][j]);
            *(float2*)(C + (ty * 8 + r) * 128 + 2 * tx + 32 * j) = v;
        }
}

// ---------------------------------------------------------------------------
// Kernel 3: trajectories. Block (bb, t): 128 batch rows x timestep t.
//   enc_traj[b, t, :] = z0[b, :] @ P[t]   (t = 0 -> copy z0)
//   z0[b, :] = enc_gt[b, 0, :]  -> row offset b * (T*K) = b * 8192
// ---------------------------------------------------------------------------
__global__ void __launch_bounds__(256, 1) traj_kernel(
    const float* __restrict__ out_gt, float* __restrict__ out_traj)
{
    const int t  = blockIdx.y;
    const int bb = blockIdx.x;
    const int tid = threadIdx.x;

    if (t == 0) {
        for (int idx = tid; idx < 4096; idx += 256) {
            int r = idx >> 5, c = (idx & 31) << 2;
            long long row = (long long)bb * 128 + r;
            float4 v = *(const float4*)(out_gt + row * 8192 + c);
            *(float4*)(out_traj + row * 8192 + c) = v;
        }
        return;
    }

    extern __shared__ float s[];
    float* sZ = s;                  // 128 x 130
    float* sB = sZ + 128 * 130;     // P[t]

    for (int idx = tid; idx < 4096; idx += 256) {
        int r = idx >> 5, c = (idx & 31) << 2;
        long long row = (long long)bb * 128 + r;
        float4 v = *(const float4*)(out_gt + row * 8192 + c);
        float* d = sZ + r * 130 + c;
        d[0] = v.x; d[1] = v.y; d[2] = v.z; d[3] = v.w;
        ((float4*)sB)[idx] = ((const float4*)g_Wpow[t])[idx];
    }
    __syncthreads();

    const int tx = tid & 15, ty = tid >> 4;
    unsigned long long acc[8][4];
    #pragma unroll
    for (int r = 0; r < 8; r++)
        #pragma unroll
        for (int j = 0; j < 4; j++) acc[r][j] = 0ULL;

    #pragma unroll 2
    for (int k = 0; k < 128; k++) {
        unsigned long long b2[4];
        #pragma unroll
        for (int j = 0; j < 4; j++)
            b2[j] = *(const unsigned long long*)(sB + k * 128 + 2 * tx + 32 * j);
        #pragma unroll
        for (int r = 0; r < 8; r++) {
            unsigned long long a2 = pack2(sZ[(ty * 8 + r) * 130 + k]);
            #pragma unroll
            for (int j = 0; j < 4; j++) ffma2(acc[r][j], a2, b2[j]);
        }
    }
    #pragma unroll
    for (int r = 0; r < 8; r++) {
        long long b = (long long)bb * 128 + ty * 8 + r;
        float* o = out_traj + b * 8192 + t * 128;
        #pragma unroll
        for (int j = 0; j < 4; j++) {
            float2 v = unpack2(acc[r][j]);
            *(float2*)(o + 2 * tx + 32 * j) = v;
        }
    }
}

// ---------------------------------------------------------------------------
// Launch: enc_gt at d_out[0 .. B*T*K), enc_traj immediately after.
// ---------------------------------------------------------------------------
extern "C" void kernel_launch(void* const* d_in, const int* in_sizes, int n_in,
                              void* d_out, int out_size)
{
    (void)in_sizes; (void)n_in; (void)out_size;
    const float* x   = (const float*)d_in[0];
    const float* W0  = (const float*)d_in[1];
    const float* b0  = (const float*)d_in[2];
    const float* W1  = (const float*)d_in[3];
    const float* b1  = (const float*)d_in[4];
    const float* W2  = (const float*)d_in[5];
    const float* koW = (const float*)d_in[6];

    float* out_gt   = (float*)d_out;
    float* out_traj = out_gt + (long long)B_DIM * T_DIM * K_DIM;

    cudaFuncSetAttribute(mlp_kernel,
                         cudaFuncAttributeMaxDynamicSharedMemorySize, SMEM_MLP);
    cudaFuncSetAttribute(pow_step_kernel,
                         cudaFuncAttributeMaxDynamicSharedMemorySize, SMEM_POW);
    cudaFuncSetAttribute(traj_kernel,
                         cudaFuncAttributeMaxDynamicSharedMemorySize, SMEM_POW);

    // ko_W powers via doubling: P[1]=W; then P[i+m] = P[i] @ P[m]
    copy_w_kernel<<<64, 256>>>(koW);
    for (int m = 1; m < 64; m <<= 1) {
        int cnt = (m < 63 - m) ? m : (63 - m);
        pow_step_kernel<<<cnt, 256, SMEM_POW>>>(m);
    }

    // Fused MLP -> enc_gt
    mlp_kernel<<<B_DIM, 256, SMEM_MLP>>>(x, W0, b0, W1, b1, W2, out_gt);

    // enc_traj[b,t,:] = z0 @ P[t]
    traj_kernel<<<dim3(64, 64), 256, SMEM_POW>>>(out_gt, out_traj);
}